// round 3
// baseline (speedup 1.0000x reference)
#include <cuda_runtime.h>
#include <math_constants.h>

// Problem shape (fixed by the dataset)
#define BB 4
#define HH 16
#define SS 2048
#define DD 64

#define BM 64   // query rows per CTA
#define BN 64   // key/value columns per tile

// Dynamic smem layout (floats):
//   qst [DD][BM]  (Q tile, transposed: qst[d][r])
//   ks  [DD][BN]  (K tile: ks[d][c])
//   vs  [BN][DD]  (V tile: vs[c][d])
//   ps  [BM][BN]  (P tile: ps[r][c])
#define SMEM_FLOATS (DD*BM + DD*BN + BN*DD + BM*BN)

__global__ __launch_bounds__(256, 2)
void attn_fused_kernel(const float* __restrict__ q,
                       const float* __restrict__ k,
                       const float* __restrict__ v,
                       const int*   __restrict__ mask,
                       float* __restrict__ out_o,   // may be null
                       float* __restrict__ out_s)   // may be null
{
    extern __shared__ float sm[];
    float* qst = sm;                       // [DD][BM]
    float* ks  = qst + DD*BM;              // [DD][BN]
    float* vs  = ks  + DD*BN;              // [BN][DD]
    float* ps  = vs  + BN*DD;              // [BM][BN]

    const int tid = threadIdx.x;
    const int tx = tid & 15;               // 0..15 -> 4 columns each
    const int ty = tid >> 4;               // 0..15 -> 4 rows each
    const int rb = blockIdx.x;             // row block (0..31)
    const int h  = blockIdx.y;
    const int b  = blockIdx.z;

    const size_t bh = (size_t)b * HH + h;
    const float* qp = q + (bh * SS + (size_t)rb * BM) * DD;  // [BM][DD]
    const float* kp = k + bh * (size_t)DD * SS;              // [DD][SS]
    const float* vp = v + bh * (size_t)SS * DD;              // [SS][DD]
    const int*   mp = mask + ((size_t)b * SS + (size_t)rb * BM) * SS; // [BM][SS]
    float* osp = out_s ? (out_s + (bh * SS + (size_t)rb * BM) * SS) : (float*)0;

    // ---- Load Q tile, transposed into smem (one-time; store conflicts OK) ----
    #pragma unroll
    for (int it = 0; it < 4; ++it) {
        int id4 = tid + it * 256;
        int r  = id4 >> 4;
        int d4 = (id4 & 15) * 4;
        float4 qv = *(const float4*)(qp + (size_t)r * DD + d4);
        qst[(d4 + 0) * BM + r] = qv.x;
        qst[(d4 + 1) * BM + r] = qv.y;
        qst[(d4 + 2) * BM + r] = qv.z;
        qst[(d4 + 3) * BM + r] = qv.w;
    }

    // ---- Online-softmax state ----
    float m_run[4], l_run[4];
    float o[4][4];
    #pragma unroll
    for (int i = 0; i < 4; ++i) {
        m_run[i] = -CUDART_INF_F;
        l_run[i] = 0.f;
        #pragma unroll
        for (int jj = 0; jj < 4; ++jj) o[i][jj] = 0.f;
    }

    for (int jt = 0; jt < SS / BN; ++jt) {
        const int s0 = jt * BN;

        __syncthreads();   // previous iter's PV readers done before overwriting tiles
        // ---- Load K and V tiles (coalesced float4) ----
        #pragma unroll
        for (int it = 0; it < 4; ++it) {
            int id4 = tid + it * 256;
            int r  = id4 >> 4;
            int c4 = (id4 & 15) * 4;
            *(float4*)(ks + r * BN + c4) = *(const float4*)(kp + (size_t)r * SS + s0 + c4);
            *(float4*)(vs + r * DD + c4) = *(const float4*)(vp + (size_t)(s0 + r) * DD + c4);
        }
        __syncthreads();

        // ---- S tile = Q*K (4x4 per thread), 2x LDS.128 + 16 FFMA per d ----
        float sacc[4][4];
        #pragma unroll
        for (int i = 0; i < 4; ++i)
            #pragma unroll
            for (int jj = 0; jj < 4; ++jj) sacc[i][jj] = 0.f;

        #pragma unroll 8
        for (int d = 0; d < DD; ++d) {
            float4 a4 = *(const float4*)(qst + d * BM + 4 * ty);
            float4 b4 = *(const float4*)(ks  + d * BN + 4 * tx);
            float av[4] = {a4.x, a4.y, a4.z, a4.w};
            float bv[4] = {b4.x, b4.y, b4.z, b4.w};
            #pragma unroll
            for (int i = 0; i < 4; ++i)
                #pragma unroll
                for (int jj = 0; jj < 4; ++jj)
                    sacc[i][jj] += av[i] * bv[jj];
        }

        // ---- Mask, scale, write scores, online softmax update, stage P ----
        #pragma unroll
        for (int ri = 0; ri < 4; ++ri) {
            const int rloc = 4 * ty + ri;
            const int4 mrow = *(const int4*)(mp + (size_t)rloc * SS + s0 + 4 * tx);
            float sv[4];
            sv[0] = (mrow.x == 0) ? -1e10f : sacc[ri][0] * 0.125f;
            sv[1] = (mrow.y == 0) ? -1e10f : sacc[ri][1] * 0.125f;
            sv[2] = (mrow.z == 0) ? -1e10f : sacc[ri][2] * 0.125f;
            sv[3] = (mrow.w == 0) ? -1e10f : sacc[ri][3] * 0.125f;
            if (osp)
                *(float4*)(osp + (size_t)rloc * SS + s0 + 4 * tx) =
                    make_float4(sv[0], sv[1], sv[2], sv[3]);

            // row max across the 16 threads of this row group
            float tm = fmaxf(fmaxf(sv[0], sv[1]), fmaxf(sv[2], sv[3]));
            #pragma unroll
            for (int off = 8; off >= 1; off >>= 1)
                tm = fmaxf(tm, __shfl_xor_sync(0xffffffffu, tm, off));

            float mn   = fmaxf(m_run[ri], tm);
            float corr = __expf(m_run[ri] - mn);   // exp(-inf)=0 on first tile
            m_run[ri]  = mn;

            float p0 = __expf(sv[0] - mn);
            float p1 = __expf(sv[1] - mn);
            float p2 = __expf(sv[2] - mn);
            float p3 = __expf(sv[3] - mn);
            float rs = (p0 + p1) + (p2 + p3);
            #pragma unroll
            for (int off = 8; off >= 1; off >>= 1)
                rs += __shfl_xor_sync(0xffffffffu, rs, off);

            l_run[ri] = l_run[ri] * corr + rs;
            #pragma unroll
            for (int jj = 0; jj < 4; ++jj) o[ri][jj] *= corr;

            *(float4*)(ps + rloc * BN + 4 * tx) = make_float4(p0, p1, p2, p3);
        }
        __syncthreads();   // ps ready

        // ---- O += P*V (4x4 per thread) ----
        #pragma unroll 8
        for (int c = 0; c < BN; ++c) {
            float4 vv = *(const float4*)(vs + c * DD + 4 * tx);
            float pr[4];
            pr[0] = ps[(4 * ty + 0) * BN + c];
            pr[1] = ps[(4 * ty + 1) * BN + c];
            pr[2] = ps[(4 * ty + 2) * BN + c];
            pr[3] = ps[(4 * ty + 3) * BN + c];
            float vvv[4] = {vv.x, vv.y, vv.z, vv.w};
            #pragma unroll
            for (int i = 0; i < 4; ++i)
                #pragma unroll
                for (int jj = 0; jj < 4; ++jj)
                    o[i][jj] += pr[i] * vvv[jj];
        }
    }

    // ---- Normalize and write O ----
    if (out_o) {
        float* op = out_o + (bh * SS + (size_t)rb * BM) * DD;
        #pragma unroll
        for (int ri = 0; ri < 4; ++ri) {
            float inv = 1.0f / l_run[ri];
            *(float4*)(op + (size_t)(4 * ty + ri) * DD + 4 * tx) =
                make_float4(o[ri][0] * inv, o[ri][1] * inv, o[ri][2] * inv, o[ri][3] * inv);
        }
    }
}

extern "C" void kernel_launch(void* const* d_in, const int* in_sizes, int n_in,
                              void* d_out, int out_size)
{
    const float* q    = (const float*)d_in[0];
    const float* k    = (const float*)d_in[1];
    const float* v    = (const float*)d_in[2];
    const int*   mask = (const int*)  d_in[3];

    const long long OUT_O_N = (long long)BB * HH * SS * DD;   // 8388608
    const long long OUT_S_N = (long long)BB * HH * SS * SS;   // 268435456

    float* o_ptr = 0;
    float* s_ptr = 0;
    if ((long long)out_size == OUT_O_N + OUT_S_N) {
        o_ptr = (float*)d_out;
        s_ptr = (float*)d_out + OUT_O_N;
    } else if ((long long)out_size == OUT_O_N) {
        o_ptr = (float*)d_out;
    } else if ((long long)out_size == OUT_S_N) {
        s_ptr = (float*)d_out;
    } else {
        o_ptr = (float*)d_out;   // fallback: at least produce the primary output
    }

    const int smem_bytes = SMEM_FLOATS * (int)sizeof(float);  // 64 KB
    cudaFuncSetAttribute(attn_fused_kernel,
                         cudaFuncAttributeMaxDynamicSharedMemorySize, smem_bytes);

    dim3 grid(SS / BM, HH, BB);   // (32, 16, 4) = 2048 CTAs
    dim3 block(256);
    attn_fused_kernel<<<grid, block, smem_bytes>>>(q, k, v, mask, o_ptr, s_ptr);
}